// round 1
// baseline (speedup 1.0000x reference)
#include <cuda_runtime.h>
#include <cuda_bf16.h>
#include <cub/cub.cuh>
#include <cstdint>

#define N_ELEMS 16777216
#define ALPHA_F 10.0f
#define DELTA_F 0.0005f
#define LUT_BITS 21
#define LUT_SIZE (1u << LUT_BITS)

// ---- scratch (device globals: allocation-free rule) ----
__device__ float g_clamped[N_ELEMS];                 // 64 MB  (sort keys in)
__device__ float g_xs[N_ELEMS];                      // 64 MB  (sorted knot x)
__device__ float g_ys[N_ELEMS];                      // 64 MB  (sorted knot y)
__device__ unsigned char g_temp[200u * 1024u * 1024u]; // CUB temp (incl. alt buffers ~134 MB)
__device__ int g_lut[LUT_SIZE + 1];                  // 8 MB bucket -> first sorted index
__device__ double g_accum;

__device__ __forceinline__ int bucket_of(float x) {
    int b = (int)(x * (float)LUT_SIZE);   // trunc-toward-zero; monotone for x >= 0
    if (b < 0) b = 0;
    if (b > (int)LUT_SIZE - 1) b = (int)LUT_SIZE - 1;
    return b;
}

__global__ void k_clamp(const float* __restrict__ indices, int n) {
    int i = blockIdx.x * blockDim.x + threadIdx.x;
    if (i == 0) g_accum = 0.0;
    if (i < n) {
        float v = indices[i];
        g_clamped[i] = fminf(fmaxf(v, 0.0f), 1.0f);
    }
}

// lut[b] = first sorted index j with bucket_of(xs[j]) >= b   (lut[LUT_SIZE] = n)
__global__ void k_lut(int n) {
    int b = blockIdx.x * blockDim.x + threadIdx.x;
    if (b > (int)LUT_SIZE) return;
    if (b == (int)LUT_SIZE) { g_lut[b] = n; return; }
    int lo = 0, hi = n;
    while (lo < hi) {
        int mid = (lo + hi) >> 1;
        if (bucket_of(g_xs[mid]) < b) lo = mid + 1; else hi = mid;
    }
    g_lut[b] = lo;
}

// np/jnp.interp semantics: j = searchsorted(xs, q, 'right') - 1 (last index with xs[j] <= q),
// left fill ys[0], right fill ys[n-1].
__device__ __forceinline__ float interp_q(float q, int n) {
    int b = bucket_of(q);
    int lo = g_lut[b];
    int hi = g_lut[b + 1];
    // find first index with xs[idx] > q within [lo, hi]
    while (lo < hi) {
        int mid = (lo + hi) >> 1;
        if (g_xs[mid] <= q) lo = mid + 1; else hi = mid;
    }
    int j = lo - 1;
    if (j < 0)      return g_ys[0];
    if (j >= n - 1) return g_ys[n - 1];
    float x0 = g_xs[j], x1 = g_xs[j + 1];
    float y0 = g_ys[j], y1 = g_ys[j + 1];
    return y0 + (q - x0) * (y1 - y0) / (x1 - x0);
}

__global__ __launch_bounds__(256) void k_query(int n) {
    int i = blockIdx.x * blockDim.x + threadIdx.x;
    float gap = 0.0f;
    if (i < n - 1) {
        float ci = g_clamped[i];
        float cn = g_clamped[i + 1];
        float f_left = interp_q(ci + DELTA_F, n);
        float f_this = interp_q(cn - DELTA_F, n);
        gap = fmaxf(f_left - f_this, 0.0f);
    }
    typedef cub::BlockReduce<float, 256> BR;
    __shared__ typename BR::TempStorage ts;
    float s = BR(ts).Sum(gap);
    if (threadIdx.x == 0) atomicAdd(&g_accum, (double)s);
}

__global__ void k_final(float* __restrict__ out) {
    out[0] = (float)((double)ALPHA_F * g_accum);
}

extern "C" void kernel_launch(void* const* d_in, const int* in_sizes, int n_in,
                              void* d_out, int out_size) {
    const float* indices = (const float*)d_in[0];
    const float* array   = (const float*)d_in[1];
    int n = in_sizes[0];

    float* p_clamped = nullptr;
    float* p_xs = nullptr;
    float* p_ys = nullptr;
    void*  p_temp = nullptr;
    cudaGetSymbolAddress((void**)&p_clamped, g_clamped);
    cudaGetSymbolAddress((void**)&p_xs, g_xs);
    cudaGetSymbolAddress((void**)&p_ys, g_ys);
    cudaGetSymbolAddress(&p_temp, g_temp);

    int threads = 256;
    int blocks = (n + threads - 1) / threads;

    // 1) clamp knots + zero accumulator
    k_clamp<<<blocks, threads>>>(indices, n);

    // 2) stable sort (keys=clamped, values=array) -> (xs, ys). Stability matches jnp.argsort ties.
    size_t temp_bytes = sizeof(g_temp);
    cub::DeviceRadixSort::SortPairs(p_temp, temp_bytes,
                                    p_clamped, p_xs,
                                    array, p_ys,
                                    n, 0, 32);

    // 3) bucket LUT over sorted xs
    int lut_blocks = ((int)LUT_SIZE + 1 + threads - 1) / threads;
    k_lut<<<lut_blocks, threads>>>(n);

    // 4) queries + reduction
    k_query<<<blocks, threads>>>(n);

    // 5) scale + write scalar output
    k_final<<<1, 1>>>((float*)d_out);
}

// round 2
// speedup vs baseline: 1.1393x; 1.1393x over previous
#include <cuda_runtime.h>
#include <cuda_bf16.h>
#include <cub/cub.cuh>
#include <cstdint>

#define N_ELEMS 16777216
#define ALPHA_F 10.0f
#define DELTA_F 0.0005f

// ---- scratch (device globals: allocation-free rule) ----
__device__ float        g_clamped[N_ELEMS];            // clamp(indices) = sort keys in
__device__ float        g_xs[N_ELEMS];                 // sorted keys
__device__ unsigned int g_idx_in[N_ELEMS];             // iota
__device__ unsigned int g_idx[N_ELEMS];                // sorted -> original index
__device__ float        g_ys[N_ELEMS];                 // array gathered into sorted order
__device__ float2       g_AB[N_ELEMS];                 // per ORIGINAL index: (f(c+d), f(c-d))
__device__ unsigned char g_temp[200u * 1024u * 1024u]; // CUB temp
__device__ double       g_accum;

__global__ void k_init(const float* __restrict__ indices, int n) {
    int i = blockIdx.x * blockDim.x + threadIdx.x;
    if (i == 0) g_accum = 0.0;
    if (i < n) {
        float v = indices[i];
        g_clamped[i] = fminf(fmaxf(v, 0.0f), 1.0f);
        g_idx_in[i] = (unsigned int)i;
    }
}

__global__ void k_gather(const float* __restrict__ array, int n) {
    int k = blockIdx.x * blockDim.x + threadIdx.x;
    if (k < n) g_ys[k] = __ldg(&array[g_idx[k]]);
}

// For each sorted position k, evaluate f at xs[k]+delta and xs[k]-delta.
// f = piecewise-linear through (xs, ys); np.interp semantics
// (j = searchsorted(xs, q, 'right') - 1; left fill ys[0], right fill ys[n-1]).
__global__ __launch_bounds__(256) void k_interp(int n) {
    int k = blockIdx.x * blockDim.x + threadIdx.x;
    if (k >= n) return;

    const float xk = __ldg(&g_xs[k]);

    // ---------- A = f(xk + delta): bracket index >= k ----------
    float qA = xk + DELTA_F;
    float A;
    {
        // gallop up: find hi with xs[hi] > qA (or hi == n)
        int off = 4096;
        while (k + off < n && __ldg(&g_xs[k + off]) <= qA) off <<= 1;
        int lo = k;                       // xs[k] <= qA
        int hi = (k + off < n) ? (k + off) : n;
        while (lo < hi) {                 // first index with xs > qA
            int mid = (lo + hi) >> 1;
            if (__ldg(&g_xs[mid]) <= qA) lo = mid + 1; else hi = mid;
        }
        int j = lo - 1;                   // j >= k >= 0
        if (j >= n - 1) {
            A = __ldg(&g_ys[n - 1]);
        } else {
            float x0 = __ldg(&g_xs[j]),     x1 = __ldg(&g_xs[j + 1]);
            float y0 = __ldg(&g_ys[j]),     y1 = __ldg(&g_ys[j + 1]);
            A = y0 + (qA - x0) * (y1 - y0) / (x1 - x0);
        }
    }

    // ---------- B = f(xk - delta): bracket index <= k-1 ----------
    float qB = xk - DELTA_F;
    float B;
    {
        // gallop down: find lo with xs[lo] <= qB (or lo == 0)
        int off = 4096;
        while (k - off > 0 && __ldg(&g_xs[k - off]) > qB) off <<= 1;
        int lo = (k - off > 0) ? (k - off) : 0;
        int hi = k;                       // xs[k] > qB (strict, delta > 0)
        while (lo < hi) {                 // first index with xs > qB
            int mid = (lo + hi) >> 1;
            if (__ldg(&g_xs[mid]) <= qB) lo = mid + 1; else hi = mid;
        }
        int j = lo - 1;
        if (j < 0) {
            B = __ldg(&g_ys[0]);
        } else if (j >= n - 1) {
            B = __ldg(&g_ys[n - 1]);
        } else {
            float x0 = __ldg(&g_xs[j]),     x1 = __ldg(&g_xs[j + 1]);
            float y0 = __ldg(&g_ys[j]),     y1 = __ldg(&g_ys[j + 1]);
            B = y0 + (qB - x0) * (y1 - y0) / (x1 - x0);
        }
    }

    // scatter to original position
    unsigned int o = __ldg(&g_idx[k]);
    g_AB[o] = make_float2(A, B);
}

// gap_i = relu(f(c_i + d) - f(c_{i+1} - d)) = relu(AB[i].x - AB[i+1].y)
__global__ __launch_bounds__(256) void k_gap(int n) {
    int i = blockIdx.x * blockDim.x + threadIdx.x;
    float gap = 0.0f;
    if (i < n - 1) {
        float2 a = g_AB[i];
        float2 b = g_AB[i + 1];
        gap = fmaxf(a.x - b.y, 0.0f);
    }
    typedef cub::BlockReduce<float, 256> BR;
    __shared__ typename BR::TempStorage ts;
    float s = BR(ts).Sum(gap);
    if (threadIdx.x == 0) atomicAdd(&g_accum, (double)s);
}

__global__ void k_final(float* __restrict__ out) {
    out[0] = (float)((double)ALPHA_F * g_accum);
}

extern "C" void kernel_launch(void* const* d_in, const int* in_sizes, int n_in,
                              void* d_out, int out_size) {
    const float* indices = (const float*)d_in[0];
    const float* array   = (const float*)d_in[1];
    int n = in_sizes[0];

    float* p_clamped = nullptr;
    float* p_xs = nullptr;
    unsigned int* p_idx_in = nullptr;
    unsigned int* p_idx = nullptr;
    void*  p_temp = nullptr;
    cudaGetSymbolAddress((void**)&p_clamped, g_clamped);
    cudaGetSymbolAddress((void**)&p_xs, g_xs);
    cudaGetSymbolAddress((void**)&p_idx_in, g_idx_in);
    cudaGetSymbolAddress((void**)&p_idx, g_idx);
    cudaGetSymbolAddress(&p_temp, g_temp);

    const int threads = 256;
    int blocks = (n + threads - 1) / threads;

    // 1) clamp + iota + zero accumulator
    k_init<<<blocks, threads>>>(indices, n);

    // 2) stable sort (key = clamped, value = original index)
    size_t temp_bytes = sizeof(g_temp);
    cub::DeviceRadixSort::SortPairs(p_temp, temp_bytes,
                                    p_clamped, p_xs,
                                    p_idx_in, p_idx,
                                    n, 0, 32);

    // 3) gather y-values into sorted order
    k_gather<<<blocks, threads>>>(array, n);

    // 4) sorted-domain interpolation, scatter (A,B) to original order
    k_interp<<<blocks, threads>>>(n);

    // 5) gap + reduction
    k_gap<<<blocks, threads>>>(n);

    // 6) scale + write scalar output
    k_final<<<1, 1>>>((float*)d_out);
}

// round 4
// speedup vs baseline: 1.1453x; 1.0053x over previous
#include <cuda_runtime.h>
#include <cuda_bf16.h>
#include <cub/cub.cuh>
#include <cstdint>

#define N_ELEMS 16777216
#define ALPHA_F 10.0f
#define DELTA_F 0.0005f
#define ITEMS 8

// ---- scratch (device globals: allocation-free rule) ----
__device__ float        g_clamped[N_ELEMS];            // clamp(indices) = sort keys in
__device__ float        g_xs[N_ELEMS];                 // sorted keys
__device__ unsigned int g_idx_in[N_ELEMS];             // iota
__device__ unsigned int g_idx[N_ELEMS];                // sorted -> original index
__device__ float        g_ys[N_ELEMS];                 // array gathered into sorted order
__device__ float2       g_AB[N_ELEMS];                 // per ORIGINAL index: (f(c+d), f(c-d))
__device__ unsigned char g_temp[200u * 1024u * 1024u]; // CUB temp
__device__ double       g_accum;

__global__ void k_init(const float* __restrict__ indices, int n) {
    int i = blockIdx.x * blockDim.x + threadIdx.x;
    if (i == 0) g_accum = 0.0;
    if (i < n) {
        float v = indices[i];
        g_clamped[i] = fminf(fmaxf(v, 0.0f), 1.0f);
        g_idx_in[i] = (unsigned int)i;
    }
}

__global__ void k_gather(const float* __restrict__ array, int n) {
    int k = blockIdx.x * blockDim.x + threadIdx.x;
    if (k < n) g_ys[k] = __ldg(&array[g_idx[k]]);
}

// Each thread owns ITEMS consecutive sorted positions. Bracket indices for
// q = xs[k] +/- delta are monotone in k: one gallop+binary search for the
// first element of the chunk, then linear pointer advance for the rest.
// np.interp semantics: j = last index with xs[j] <= q; left fill ys[0],
// right fill ys[n-1]. (Bracket always has x1 > q >= x0 -> x1 > x0, no div0.)
__global__ __launch_bounds__(256) void k_interp(int n) {
    const int base = (blockIdx.x * 256 + threadIdx.x) * ITEMS;
    if (base >= n) return;
    const int m = (n - base < ITEMS) ? (n - base) : ITEMS;

    float xk[ITEMS];
    #pragma unroll
    for (int t = 0; t < ITEMS; t++)
        xk[t] = (t < m) ? __ldg(&g_xs[base + t]) : 0.0f;

    float A[ITEMS], B[ITEMS];

    // ---------- side A: q = xk + delta, bracket >= k ----------
    {
        float q0 = xk[0] + DELTA_F;
        int lo = base;                       // xs[base] <= q0
        int off = 8192;
        while (base + off < n && __ldg(&g_xs[base + off]) <= q0) off <<= 1;
        int hi = (base + off < n) ? (base + off) : n;
        while (lo < hi) {                    // first index with xs > q0
            int mid = (lo + hi) >> 1;
            if (__ldg(&g_xs[mid]) <= q0) lo = mid + 1; else hi = mid;
        }
        int jA = lo - 1;                     // exact bracket for k = base
        #pragma unroll
        for (int t = 0; t < ITEMS; t++) {
            if (t >= m) break;
            float q = xk[t] + DELTA_F;
            while (jA + 1 < n && __ldg(&g_xs[jA + 1]) <= q) jA++;
            if (jA >= n - 1) {
                A[t] = __ldg(&g_ys[n - 1]);
            } else {
                float x0 = __ldg(&g_xs[jA]), x1 = __ldg(&g_xs[jA + 1]);
                float y0 = __ldg(&g_ys[jA]), y1 = __ldg(&g_ys[jA + 1]);
                A[t] = y0 + (q - x0) * (y1 - y0) / (x1 - x0);
            }
        }
    }

    // ---------- side B: q = xk - delta, bracket <= k-1 ----------
    {
        float q0 = xk[0] - DELTA_F;
        int off = 8192;
        while (base - off >= 0 && __ldg(&g_xs[base - off]) > q0) off <<= 1;
        int lo = (base - off > 0) ? (base - off) : 0;
        int hi = base;                       // xs[base] > q0 (delta > 0)
        while (lo < hi) {                    // first index with xs > q0
            int mid = (lo + hi) >> 1;
            if (__ldg(&g_xs[mid]) <= q0) lo = mid + 1; else hi = mid;
        }
        int jB = lo - 1;                     // in [-1, base-1], exact for k = base
        #pragma unroll
        for (int t = 0; t < ITEMS; t++) {
            if (t >= m) break;
            float q = xk[t] - DELTA_F;
            while (jB + 1 < n && __ldg(&g_xs[jB + 1]) <= q) jB++;
            if (jB < 0) {
                B[t] = __ldg(&g_ys[0]);
            } else if (jB >= n - 1) {
                B[t] = __ldg(&g_ys[n - 1]);
            } else {
                float x0 = __ldg(&g_xs[jB]), x1 = __ldg(&g_xs[jB + 1]);
                float y0 = __ldg(&g_ys[jB]), y1 = __ldg(&g_ys[jB + 1]);
                B[t] = y0 + (q - x0) * (y1 - y0) / (x1 - x0);
            }
        }
    }

    // scatter to original positions
    #pragma unroll
    for (int t = 0; t < ITEMS; t++) {
        if (t >= m) break;
        unsigned int o = __ldg(&g_idx[base + t]);
        g_AB[o] = make_float2(A[t], B[t]);
    }
}

// gap_i = relu(f(c_i + d) - f(c_{i+1} - d)) = relu(AB[i].x - AB[i+1].y)
__global__ __launch_bounds__(256) void k_gap(int n) {
    int i = blockIdx.x * blockDim.x + threadIdx.x;
    float gap = 0.0f;
    if (i < n - 1) {
        float2 a = g_AB[i];
        float2 b = g_AB[i + 1];
        gap = fmaxf(a.x - b.y, 0.0f);
    }
    typedef cub::BlockReduce<float, 256> BR;
    __shared__ typename BR::TempStorage ts;
    float s = BR(ts).Sum(gap);
    if (threadIdx.x == 0) atomicAdd(&g_accum, (double)s);
}

__global__ void k_final(float* __restrict__ out) {
    out[0] = (float)((double)ALPHA_F * g_accum);
}

extern "C" void kernel_launch(void* const* d_in, const int* in_sizes, int n_in,
                              void* d_out, int out_size) {
    const float* indices = (const float*)d_in[0];
    const float* array   = (const float*)d_in[1];
    int n = in_sizes[0];

    float* p_clamped = nullptr;
    float* p_xs = nullptr;
    unsigned int* p_idx_in = nullptr;
    unsigned int* p_idx = nullptr;
    void*  p_temp = nullptr;
    cudaGetSymbolAddress((void**)&p_clamped, g_clamped);
    cudaGetSymbolAddress((void**)&p_xs, g_xs);
    cudaGetSymbolAddress((void**)&p_idx_in, g_idx_in);
    cudaGetSymbolAddress((void**)&p_idx, g_idx);
    cudaGetSymbolAddress(&p_temp, g_temp);

    const int threads = 256;
    int blocks = (n + threads - 1) / threads;

    // 1) clamp + iota + zero accumulator
    k_init<<<blocks, threads>>>(indices, n);

    // 2) stable sort (key = clamped, value = original index)
    size_t temp_bytes = sizeof(g_temp);
    cub::DeviceRadixSort::SortPairs(p_temp, temp_bytes,
                                    p_clamped, p_xs,
                                    p_idx_in, p_idx,
                                    n, 0, 32);

    // 3) gather y-values into sorted order
    k_gather<<<blocks, threads>>>(array, n);

    // 4) sorted-domain merge-interpolation, scatter (A,B) to original order
    int chunk_blocks = (n + threads * ITEMS - 1) / (threads * ITEMS);
    k_interp<<<chunk_blocks, threads>>>(n);

    // 5) gap + reduction
    k_gap<<<blocks, threads>>>(n);

    // 6) scale + write scalar output
    k_final<<<1, 1>>>((float*)d_out);
}